// round 10
// baseline (speedup 1.0000x reference)
#include <cuda_runtime.h>
#include <cuda_bf16.h>
#include <cuda_fp16.h>
#include <cstdint>

#define NB 256
#define HW 256
#define OFF_C1 512
#define OFF_C2 (512 + 16777216)

// int8 geometry: rows of 32 ic (+16B pad) = 48B; chunk = 256px*48B = 12288B; 32 chunks
#define XCHB   12288
#define IMGB   393216                 // 32*12288
#define WCHB   55296                  // 9*128*48
#define OCBB   1769472                // 32*55296
// conv smem map
#define XS0 0
#define XS1 12336                     // 12288 + 48 zero row
#define WS0 24672
#define WS1 79968
#define MBOFF   135264
#define PARTOFF 135296
#define SMEMC   (135296 + 69632)      // + 256*136 half partials = 204928

// ---------------- device scratch ----------------
__device__ char          g_XIN[(size_t)NB * IMGB];          // conv1 int8 input
__device__ char          g_X2 [(size_t)NB * IMGB];          // conv2 int8 input
__device__ __nv_bfloat16 g_Y1 [(size_t)NB * 64 * 6144];     // conv1 out bf16 [img][64c16][256][24]
__device__ __nv_bfloat16 g_Y2 [(size_t)NB * 32 * 6144];
__device__ char          g_W1q[(size_t)8 * OCBB];
__device__ char          g_W2q[(size_t)4 * OCBB];
__device__ float         g_sv1a[1024], g_sv1c[1024], g_sv2[512], g_sv2c[512];
__device__ float         g_y1max[NB];
__device__ float         g_invn1[NB * HW];
__device__ float         g_invn2[NB * HW];
__device__ float         g_wclsT[512 * 512];

// ---------------- PTX helpers ----------------
__device__ __forceinline__ uint32_t smem_u32(const void* p) {
    uint32_t a;
    asm("{ .reg .u64 t; cvta.to.shared.u64 t, %1; cvt.u32.u64 %0, t; }" : "=r"(a) : "l"(p));
    return a;
}
#define MBAR_INIT(a, c)  asm volatile("mbarrier.init.shared.b64 [%0], %1;" :: "r"(a), "r"((uint32_t)(c)) : "memory")
#define MBAR_EXPECT_TX(a, n) \
    asm volatile("mbarrier.arrive.expect_tx.shared.b64 _, [%0], %1;" :: "r"(a), "r"((uint32_t)(n)) : "memory")
#define MBAR_WAIT(a, par) do {                                                    \
    uint32_t _m = (a), _p = (par), _d;                                            \
    asm volatile("{\n\t.reg .pred p;\n\t"                                         \
        "mbarrier.try_wait.parity.acquire.cta.shared::cta.b64 p, [%1], %2;\n\t"   \
        "selp.b32 %0,1,0,p;\n\t}" : "=r"(_d) : "r"(_m), "r"(_p) : "memory");      \
    if (!_d) {                                                                    \
        asm volatile("{\n\t.reg .pred P1;\n\tWL_%=:\n\t"                          \
            "mbarrier.try_wait.parity.acquire.cta.shared::cta.b64 P1, [%0], %1, 0x989680;\n\t" \
            "@P1 bra.uni WD_%=;\n\tbra.uni WL_%=;\n\tWD_%=:\n\t}"                 \
            :: "r"(_m), "r"(_p) : "memory");                                      \
    }                                                                             \
} while (0)
#define BULK_G2S(dst, src, bytes, bar) \
    asm volatile("cp.async.bulk.shared::cta.global.mbarrier::complete_tx::bytes [%0], [%1], %2, [%3];" \
        :: "r"(dst), "l"(src), "r"((uint32_t)(bytes)), "r"(bar) : "memory")
#define LDSM4(r0, r1, r2, r3, a) \
    asm volatile("ldmatrix.sync.aligned.m8n8.x4.shared.b16 {%0,%1,%2,%3}, [%4];" \
        : "=r"(r0), "=r"(r1), "=r"(r2), "=r"(r3) : "r"(a))
__device__ __forceinline__ void imma16832(int* c, const uint32_t* a, uint32_t b0, uint32_t b1) {
    asm volatile(
        "mma.sync.aligned.m16n8k32.row.col.s32.s8.s8.s32 "
        "{%0,%1,%2,%3}, {%4,%5,%6,%7}, {%8,%9}, {%0,%1,%2,%3};\n"
        : "+r"(c[0]), "+r"(c[1]), "+r"(c[2]), "+r"(c[3])
        : "r"(a[0]), "r"(a[1]), "r"(a[2]), "r"(a[3]), "r"(b0), "r"(b1));
}

// ---------------- K0a: zero per-image max ----------------
__global__ void k_zero(float* m) { m[threadIdx.x] = 0.f; }

// ---------------- K0: relu + channel norms + int8 chunks 0..15 ----------------
__global__ void k_norm(const float* __restrict__ f1, const float* __restrict__ f2,
                       char* __restrict__ x,
                       float* __restrict__ invn1, float* __restrict__ invn2) {
    int b = blockIdx.x, p = threadIdx.x;
    const float* f1b = f1 + (size_t)b * 65536;
    const float* f2b = f2 + (size_t)b * 65536;
    char* xb = x + (size_t)b * IMGB;
    float s1 = 0.f, s2 = 0.f;
    const float qs = 127.f / 6.f;
    for (int ch = 0; ch < 8; ++ch) {
        unsigned char c1[32], c2[32];
        #pragma unroll
        for (int i = 0; i < 32; ++i) {
            float v1 = fmaxf(f1b[(ch * 32 + i) * HW + p], 0.f);
            float v2 = fmaxf(f2b[(ch * 32 + i) * HW + p], 0.f);
            s1 += v1 * v1;  s2 += v2 * v2;
            int q1 = __float2int_rn(v1 * qs);  c1[i] = (unsigned char)min(q1, 127);
            int q2 = __float2int_rn(v2 * qs);  c2[i] = (unsigned char)min(q2, 127);
        }
        *(uint4*)(xb + (size_t)ch * XCHB + p * 48)            = *(uint4*)&c1[0];
        *(uint4*)(xb + (size_t)ch * XCHB + p * 48 + 16)       = *(uint4*)&c1[16];
        *(uint4*)(xb + (size_t)(8 + ch) * XCHB + p * 48)      = *(uint4*)&c2[0];
        *(uint4*)(xb + (size_t)(8 + ch) * XCHB + p * 48 + 16) = *(uint4*)&c2[16];
    }
    invn1[b * HW + p] = 1.0f / fmaxf(sqrtf(s1), 1e-12f);
    invn2[b * HW + p] = 1.0f / fmaxf(sqrtf(s2), 1e-12f);
}

// ---------------- weight scale reduction (per-oc, per-group) ----------------
__global__ void k_wmax(const float* __restrict__ w, float* svA, float* svC, int grouped) {
    int oc = blockIdx.x, t = threadIdx.x;
    float mA = 0.f, mC = 0.f;
    for (int e = t; e < 9216; e += 256) {
        float v = fabsf(w[(size_t)oc * 9216 + e]);
        if (grouped) {
            int ic = e / 9;
            bool rg = (ic < 256) || (ic >= 512 && ic < 768);
            if (rg) mA = fmaxf(mA, v * (6.f / 127.f));
            else    mC = fmaxf(mC, v * (1.f / 127.f));
        } else {
            mA = fmaxf(mA, v);
        }
    }
    __shared__ float sA[256], sC[256];
    sA[t] = mA; sC[t] = mC;
    __syncthreads();
    for (int s = 128; s > 0; s >>= 1) {
        if (t < s) { sA[t] = fmaxf(sA[t], sA[t + s]); sC[t] = fmaxf(sC[t], sC[t + s]); }
        __syncthreads();
    }
    if (t == 0) {
        svA[oc] = fmaxf(sA[0], 1e-20f) * (1.f / 127.f);
        svC[oc] = fmaxf(sC[0], 1e-20f) * (1.f / 127.f);
    }
}

// ---------------- weight quantize: [ocb][cc32][tap][128][48] ----------------
__global__ void k_wq(const float* __restrict__ w, const float* __restrict__ svA,
                     const float* __restrict__ svC, char* __restrict__ o,
                     int remap, int total) {
    int idx = blockIdx.x * blockDim.x + threadIdx.x;
    if (idx >= total) return;
    int j   = idx % 48;
    int r   = (idx / 48) % 128;
    int tap = (idx / 6144) % 9;
    int cc  = (idx / 55296) % 32;
    int ocb = idx / 1769472;
    char q = 0;
    if (j < 32) {
        int oc = ocb * 128 + r;
        int ic; float sx, sv;
        if (remap) {
            if (cc < 8)       { ic = cc * 32 + j;              sx = 6.f / 127.f; sv = svA[oc]; }
            else if (cc < 16) { ic = 512 + (cc - 8) * 32 + j;  sx = 6.f / 127.f; sv = svA[oc]; }
            else if (cc < 24) { ic = 256 + (cc - 16) * 32 + j; sx = 1.f / 127.f; sv = svC[oc]; }
            else              { ic = 768 + (cc - 24) * 32 + j; sx = 1.f / 127.f; sv = svC[oc]; }
        } else { ic = cc * 32 + j; sx = 1.f; sv = svA[oc]; }
        float v = w[(size_t)oc * 9216 + (size_t)ic * 9 + tap] * sx / sv;
        int qi = __float2int_rn(v);
        qi = max(-127, min(127, qi));
        q = (char)qi;
    }
    o[idx] = q;
}

__global__ void k_prepcls(const float* __restrict__ w, float* __restrict__ o) {
    int idx = blockIdx.x * blockDim.x + threadIdx.x;
    if (idx >= 512 * 512) return;
    int ic = idx >> 9, oc = idx & 511;
    o[idx] = w[oc * 512 + ic];
}

// ---------------- K1: correlation GEMM (fp32 outputs + int8 chunks 16..31) ----------------
__global__ void __launch_bounds__(256) k_corr(
        const float* __restrict__ f1, const float* __restrict__ f2,
        float* __restrict__ out,
        const float* __restrict__ invn1, const float* __restrict__ invn2,
        char* __restrict__ x) {
    __shared__ float A_s[16][132];
    __shared__ float B_s[16][132];
    int b = blockIdx.x, q = blockIdx.y;
    int kb = (q >> 1) * 128, pb = (q & 1) * 128;
    int t = threadIdx.x, tx = t & 15, ty = t >> 4;
    const float* f1b = f1 + (size_t)b * 65536;
    const float* f2b = f2 + (size_t)b * 65536;
    float acc[8][8];
    #pragma unroll
    for (int i = 0; i < 8; ++i)
        #pragma unroll
        for (int j = 0; j < 8; ++j) acc[i][j] = 0.f;
    for (int cc = 0; cc < 16; ++cc) {
        #pragma unroll
        for (int u = 0; u < 8; ++u) {
            int e = t + 256 * u;
            int c = e >> 7, k = e & 127;
            A_s[c][k] = fmaxf(f2b[(cc * 16 + c) * HW + kb + k], 0.f);
            B_s[c][k] = fmaxf(f1b[(cc * 16 + c) * HW + pb + k], 0.f);
        }
        __syncthreads();
        #pragma unroll
        for (int c = 0; c < 16; ++c) {
            float4 a0 = *(const float4*)&A_s[c][ty * 8];
            float4 a1 = *(const float4*)&A_s[c][ty * 8 + 4];
            float4 b0 = *(const float4*)&B_s[c][tx * 8];
            float4 b1 = *(const float4*)&B_s[c][tx * 8 + 4];
            float av[8] = {a0.x, a0.y, a0.z, a0.w, a1.x, a1.y, a1.z, a1.w};
            float bv[8] = {b0.x, b0.y, b0.z, b0.w, b1.x, b1.y, b1.z, b1.w};
            #pragma unroll
            for (int i = 0; i < 8; ++i)
                #pragma unroll
                for (int j = 0; j < 8; ++j) acc[i][j] += av[i] * bv[j];
        }
        __syncthreads();
    }
    float ik[8], ip[8];
    #pragma unroll
    for (int i = 0; i < 8; ++i) ik[i] = invn2[b * HW + kb + ty * 8 + i];
    #pragma unroll
    for (int j = 0; j < 8; ++j) ip[j] = invn1[b * HW + pb + tx * 8 + j];

    float vm[8][8];
    #pragma unroll
    for (int i = 0; i < 8; ++i)
        #pragma unroll
        for (int j = 0; j < 8; ++j) vm[i][j] = acc[i][j] * ik[i] * ip[j];

    float* c1 = out + OFF_C1 + (size_t)b * 65536;
    float* c2 = out + OFF_C2 + (size_t)b * 65536;
    #pragma unroll
    for (int i = 0; i < 8; ++i) {
        int k = kb + ty * 8 + i;
        #pragma unroll
        for (int j = 0; j < 8; ++j) {
            int p = pb + tx * 8 + j;
            c1[k * HW + p] = vm[i][j];
            c2[p * HW + k] = vm[i][j];
        }
    }
    // int8 copies: corr1 -> chunks 16..23 (row=p, byte=k&31), corr2 -> 24..31 (row=k, byte=p&31)
    char* xb = x + (size_t)b * IMGB;
    int k0 = kb + ty * 8;
    int ch1 = 16 + (k0 >> 5), jo1 = k0 & 31;
    #pragma unroll
    for (int j = 0; j < 8; ++j) {
        int p = pb + tx * 8 + j;
        unsigned char q8[8];
        #pragma unroll
        for (int i = 0; i < 8; ++i) {
            int qi = __float2int_rn(vm[i][j] * 127.f);
            q8[i] = (unsigned char)min(max(qi, 0), 127);
        }
        *(uint2*)(xb + (size_t)ch1 * XCHB + p * 48 + jo1) = *(uint2*)&q8[0];
    }
    int p0 = pb + tx * 8;
    int ch2 = 24 + (p0 >> 5), jo2 = p0 & 31;
    #pragma unroll
    for (int i = 0; i < 8; ++i) {
        int k = kb + ty * 8 + i;
        unsigned char q8[8];
        #pragma unroll
        for (int j = 0; j < 8; ++j) {
            int qi = __float2int_rn(vm[i][j] * 127.f);
            q8[j] = (unsigned char)min(max(qi, 0), 127);
        }
        *(uint2*)(xb + (size_t)ch2 * XCHB + k * 48 + jo2) = *(uint2*)&q8[0];
    }
}

// ---------------- int8 conv 3x3 implicit GEMM (IMMA + bulk-copy double buffer) ----------------
// grid (OC/128, NB), 512 threads. Two-phase per-group accumulation with fp16 partial in smem.
__global__ void __launch_bounds__(512, 1) k_conv(
        const char* __restrict__ Xg,    // [img][32][256][48]
        const char* __restrict__ Wq,    // [ocb][32][9][128][48]
        const float* __restrict__ svA, const float* __restrict__ svC,
        const float* __restrict__ bias,
        const float* __restrict__ smaxIn,   // per-image input max (conv2) or null
        float* __restrict__ amaxOut,        // per-image output max atomic (conv1) or null
        __nv_bfloat16* __restrict__ Y,      // [img][OC/16][256][24] bf16
        int OC, int SPLIT) {
    extern __shared__ __align__(16) char sraw[];
    uint32_t sb = smem_u32(sraw);
    int img = blockIdx.y, ocb = blockIdx.x;
    int t = threadIdx.x, lane = t & 31, wid = t >> 5;
    int g = lane >> 2, tg = lane & 3;
    int wm = (wid & 3) * 32, wn = (wid >> 2) * 64;

    const char* xg = Xg + (size_t)img * IMGB;
    const char* wg = Wq + (size_t)ocb * OCBB;

    uint32_t FB0 = sb + MBOFF, FB1 = sb + MBOFF + 8;
    if (t == 0) { MBAR_INIT(FB0, 1); MBAR_INIT(FB1, 1); }
    if (t < 24) {   // zero halo rows
        int bi = t / 12, w = t % 12;
        *(uint32_t*)(sraw + (bi ? XS1 : XS0) + 12288 + w * 4) = 0u;
    }
    __syncthreads();
    if (t == 0) {
        #pragma unroll
        for (int s = 0; s < 2; ++s) {
            uint32_t fb = s ? FB1 : FB0;
            MBAR_EXPECT_TX(fb, 12288 + 55296);
            BULK_G2S(sb + (s ? XS1 : XS0), xg + (size_t)s * XCHB, 12288, fb);
            BULK_G2S(sb + (s ? WS1 : WS0), wg + (size_t)s * WCHB, 55296, fb);
        }
    }

    // per-lane ldmatrix address prep (identical geometry to bf16 k16: 48B rows, 16B segs)
    int r8 = lane & 7;
    uint32_t q1 = (lane >> 3) & 1;
    int      q2 = (lane >> 4) & 1;
    uint32_t arel = (uint32_t)(wm + r8 + ((lane & 8) ? 8 : 0)) * 48 + ((lane & 16) ? 16 : 0);
    uint32_t xrel[4], mv[4];
    #pragma unroll
    for (int jj = 0; jj < 4; ++jj) {
        int px = wn + (2 * jj + q2) * 8 + r8;
        xrel[jj] = (uint32_t)px * 48 + q1 * 16;
        int xx = px & 15, yy = px >> 4;
        uint32_t m = 0;
        #pragma unroll
        for (int tp = 0; tp < 9; ++tp) {
            int dy = tp / 3 - 1, dx = tp % 3 - 1;
            if ((unsigned)(xx + dx) < 16u && (unsigned)(yy + dy) < 16u) m |= 1u << tp;
        }
        mv[jj] = m;
    }

    // per-thread output scales
    float vA[2][2], vC[2][2];
    #pragma unroll
    for (int mi = 0; mi < 2; ++mi) {
        int oc0 = ocb * 128 + wm + mi * 16 + g;
        vA[mi][0] = svA[oc0];  vA[mi][1] = svA[oc0 + 8];
        vC[mi][0] = svC[oc0];  vC[mi][1] = svC[oc0 + 8];
    }

    int acc[2][8][4];
    #pragma unroll
    for (int mi = 0; mi < 2; ++mi)
        #pragma unroll
        for (int j = 0; j < 8; ++j)
            #pragma unroll
            for (int r = 0; r < 4; ++r) acc[mi][j][r] = 0;

    __half* PART = (__half*)(sraw + PARTOFF);

    for (int cc = 0; cc < 32; ++cc) {
        int p = cc & 1, ph = (cc >> 1) & 1;
        MBAR_WAIT(p ? FB1 : FB0, ph);

        uint32_t Xa = sb + (p ? XS1 : XS0);
        uint32_t Wa = sb + (p ? WS1 : WS0);
        uint32_t za = Xa + 12288 + q1 * 16;
        uint32_t bb0 = Xa + xrel[0], bb1 = Xa + xrel[1];
        uint32_t bb2 = Xa + xrel[2], bb3 = Xa + xrel[3];
        uint32_t aA = Wa + arel;

        #pragma unroll
        for (int tp = 0; tp < 9; ++tp) {
            const int dy = tp / 3 - 1, dx = tp % 3 - 1;
            const int off = (dy * 16 + dx) * 48;
            uint32_t a0[4], a1[4];
            LDSM4(a0[0], a0[1], a0[2], a0[3], aA + tp * 6144);
            LDSM4(a1[0], a1[1], a1[2], a1[3], aA + tp * 6144 + 768);
            uint32_t bbv[4] = {bb0, bb1, bb2, bb3};
            #pragma unroll
            for (int jj = 0; jj < 4; ++jj) {
                uint32_t ba = ((mv[jj] >> tp) & 1u) ? (uint32_t)(bbv[jj] + off) : za;
                uint32_t b0, b1, b2, b3;
                LDSM4(b0, b1, b2, b3, ba);
                imma16832(acc[0][2 * jj],     a0, b0, b1);
                imma16832(acc[1][2 * jj],     a1, b0, b1);
                imma16832(acc[0][2 * jj + 1], a0, b2, b3);
                imma16832(acc[1][2 * jj + 1], a1, b2, b3);
            }
        }

        __syncthreads();
        if (t == 0 && cc + 2 < 32) {
            int nn = cc + 2;
            uint32_t fb = p ? FB1 : FB0;
            MBAR_EXPECT_TX(fb, 12288 + 55296);
            BULK_G2S(Xa, xg + (size_t)nn * XCHB, 12288, fb);
            BULK_G2S(Wa, wg + (size_t)nn * WCHB, 55296, fb);
        }

        if (cc == SPLIT - 1) {
            // park group-A partial (scaled float) as fp16, reset accumulators
            #pragma unroll
            for (int mi = 0; mi < 2; ++mi) {
                int ocl = wm + mi * 16 + g;
                #pragma unroll
                for (int j = 0; j < 8; ++j) {
                    int px = wn + j * 8 + 2 * tg;
                    int* ac = acc[mi][j];
                    PART[px * 136 + ocl]           = __float2half((float)ac[0] * vA[mi][0]);
                    PART[(px + 1) * 136 + ocl]     = __float2half((float)ac[1] * vA[mi][0]);
                    PART[px * 136 + ocl + 8]       = __float2half((float)ac[2] * vA[mi][1]);
                    PART[(px + 1) * 136 + ocl + 8] = __float2half((float)ac[3] * vA[mi][1]);
                    ac[0] = 0; ac[1] = 0; ac[2] = 0; ac[3] = 0;
                }
            }
        }
    }

    // epilogue: combine partial + group-C acc, bias, relu, bf16, transpose, store
    __syncthreads();
    float sIn = smaxIn ? smaxIn[img] * (1.f / 127.f) : 1.f;
    float lmax = 0.f;
    __nv_bfloat16* Sh = (__nv_bfloat16*)sraw;   // [256 px][136]
    #pragma unroll
    for (int mi = 0; mi < 2; ++mi) {
        int ocl = wm + mi * 16 + g;
        float bz0 = bias[ocb * 128 + ocl];
        float bz1 = bias[ocb * 128 + ocl + 8];
        #pragma unroll
        for (int j = 0; j < 8; ++j) {
            int px = wn + j * 8 + 2 * tg;
            const int* ac = acc[mi][j];
            float v0 = fmaxf(sIn * (__half2float(PART[px * 136 + ocl])           + vC[mi][0] * ac[0]) + bz0, 0.f);
            float v1 = fmaxf(sIn * (__half2float(PART[(px + 1) * 136 + ocl])     + vC[mi][0] * ac[1]) + bz0, 0.f);
            float v2 = fmaxf(sIn * (__half2float(PART[px * 136 + ocl + 8])       + vC[mi][1] * ac[2]) + bz1, 0.f);
            float v3 = fmaxf(sIn * (__half2float(PART[(px + 1) * 136 + ocl + 8]) + vC[mi][1] * ac[3]) + bz1, 0.f);
            lmax = fmaxf(lmax, fmaxf(fmaxf(v0, v1), fmaxf(v2, v3)));
            Sh[px * 136 + ocl]           = __float2bfloat16(v0);
            Sh[(px + 1) * 136 + ocl]     = __float2bfloat16(v1);
            Sh[px * 136 + ocl + 8]       = __float2bfloat16(v2);
            Sh[(px + 1) * 136 + ocl + 8] = __float2bfloat16(v3);
        }
    }
    if (amaxOut) {
        #pragma unroll
        for (int o = 16; o > 0; o >>= 1)
            lmax = fmaxf(lmax, __shfl_xor_sync(0xffffffffu, lmax, o));
        if (lane == 0) atomicMax((unsigned int*)&amaxOut[img], __float_as_uint(lmax));
    }
    __syncthreads();
    __nv_bfloat16* Yb = Y + ((size_t)img * (OC >> 4) + ocb * 8) * 6144;
    #pragma unroll
    for (int k2 = 0; k2 < 8; ++k2) {
        int idx = t + 512 * k2;
        int c8 = idx >> 9, rem = idx & 511, px = rem >> 1, hf = rem & 1;
        uint4 v = *(uint4*)&Sh[px * 136 + c8 * 16 + hf * 8];
        *(uint4*)&Yb[((size_t)c8 * 256 + px) * 24 + hf * 8] = v;
    }
}

// ---------------- quantize Y1 -> int8 X2 (per-image scale) ----------------
__global__ void k_qy1(const __nv_bfloat16* __restrict__ Y1, const float* __restrict__ ymax,
                      char* __restrict__ X2) {
    int img = blockIdx.x, p = threadIdx.x;
    float m = ymax[img];
    float inv = m > 0.f ? 127.f / m : 0.f;
    const __nv_bfloat16* yb = Y1 + (size_t)img * 64 * 6144;
    char* xb = X2 + (size_t)img * IMGB;
    for (int cc = 0; cc < 32; ++cc) {
        unsigned char q[32];
        #pragma unroll
        for (int h = 0; h < 2; ++h) {
            __nv_bfloat16 hv[16];
            const __nv_bfloat16* src = yb + (size_t)(2 * cc + h) * 6144 + p * 24;
            *(uint4*)&hv[0] = *(const uint4*)&src[0];
            *(uint4*)&hv[8] = *(const uint4*)&src[8];
            #pragma unroll
            for (int i = 0; i < 16; ++i) {
                int qi = __float2int_rn(__bfloat162float(hv[i]) * inv);
                q[h * 16 + i] = (unsigned char)min(qi, 127);
            }
        }
        *(uint4*)(xb + (size_t)cc * XCHB + p * 48)      = *(uint4*)&q[0];
        *(uint4*)(xb + (size_t)cc * XCHB + p * 48 + 16) = *(uint4*)&q[16];
    }
}

// ---------------- final head: 1x1 (diag) + avgpool + softmax ----------------
__global__ void k_final(const __nv_bfloat16* __restrict__ Y2,
                        const float* __restrict__ wT,
                        float* __restrict__ out) {
    int b = blockIdx.x, p = threadIdx.x;
    const __nv_bfloat16* yb = Y2 + (size_t)b * 32 * 6144;
    float a0 = 0.f, a1 = 0.f;
    for (int c = 0; c < 32; ++c) {
        __nv_bfloat16 h[16];
        *(uint4*)&h[0] = *(const uint4*)&yb[((size_t)c * 256 + p) * 24];
        *(uint4*)&h[8] = *(const uint4*)&yb[((size_t)c * 256 + p) * 24 + 8];
        const float* wr = wT + (size_t)c * 16 * 512 + p;
        #pragma unroll
        for (int i = 0; i < 16; ++i) {
            float y = __bfloat162float(h[i]);
            a0 += wr[i * 512] * y;
            a1 += wr[i * 512 + 256] * y;
        }
    }
    a0 = fmaxf(a0, 0.f);
    a1 = fmaxf(a1, 0.f);
    __shared__ float s0[256], s1[256];
    s0[p] = a0; s1[p] = a1;
    __syncthreads();
    for (int st = 128; st > 0; st >>= 1) {
        if (p < st) { s0[p] += s0[p + st]; s1[p] += s1[p + st]; }
        __syncthreads();
    }
    if (p == 0) {
        float m0 = s0[0] * (1.0f / 256.0f);
        float m1 = s1[0] * (1.0f / 256.0f);
        float mx = fmaxf(m0, m1);
        float e0 = expf(m0 - mx), e1 = expf(m1 - mx);
        float inv = 1.0f / (e0 + e1);
        out[b * 2 + 0] = e0 * inv;
        out[b * 2 + 1] = e1 * inv;
    }
}

// ---------------- launch ----------------
extern "C" void kernel_launch(void* const* d_in, const int* in_sizes, int n_in,
                              void* d_out, int out_size) {
    const float* f1      = (const float*)d_in[0];
    const float* f2      = (const float*)d_in[1];
    const float* conv1_w = (const float*)d_in[2];
    const float* conv1_b = (const float*)d_in[3];
    const float* conv2_w = (const float*)d_in[4];
    const float* conv2_b = (const float*)d_in[5];
    const float* cls_w   = (const float*)d_in[6];
    float* out = (float*)d_out;

    char *xin, *x2, *w1q, *w2q;
    __nv_bfloat16 *y1, *y2;
    float *invn1, *invn2, *wclsT, *sv1a, *sv1c, *sv2, *sv2c, *y1max;
    cudaGetSymbolAddress((void**)&xin,   g_XIN);
    cudaGetSymbolAddress((void**)&x2,    g_X2);
    cudaGetSymbolAddress((void**)&y1,    g_Y1);
    cudaGetSymbolAddress((void**)&y2,    g_Y2);
    cudaGetSymbolAddress((void**)&w1q,   g_W1q);
    cudaGetSymbolAddress((void**)&w2q,   g_W2q);
    cudaGetSymbolAddress((void**)&invn1, g_invn1);
    cudaGetSymbolAddress((void**)&invn2, g_invn2);
    cudaGetSymbolAddress((void**)&wclsT, g_wclsT);
    cudaGetSymbolAddress((void**)&sv1a,  g_sv1a);
    cudaGetSymbolAddress((void**)&sv1c,  g_sv1c);
    cudaGetSymbolAddress((void**)&sv2,   g_sv2);
    cudaGetSymbolAddress((void**)&sv2c,  g_sv2c);
    cudaGetSymbolAddress((void**)&y1max, g_y1max);

    cudaFuncSetAttribute(k_conv, cudaFuncAttributeMaxDynamicSharedMemorySize, SMEMC);

    k_zero<<<1, NB>>>(y1max);
    k_norm<<<NB, 256>>>(f1, f2, xin, invn1, invn2);
    k_wmax<<<1024, 256>>>(conv1_w, sv1a, sv1c, 1);
    k_wq<<<(8 * 1769472 + 255) / 256, 256>>>(conv1_w, sv1a, sv1c, w1q, 1, 8 * 1769472);
    k_wmax<<<512, 256>>>(conv2_w, sv2, sv2c, 0);
    k_wq<<<(4 * 1769472 + 255) / 256, 256>>>(conv2_w, sv2, sv2c, w2q, 0, 4 * 1769472);
    k_prepcls<<<(512 * 512 + 255) / 256, 256>>>(cls_w, wclsT);

    k_corr<<<dim3(NB, 4), 256>>>(f1, f2, out, invn1, invn2, xin);

    k_conv<<<dim3(8, NB), 512, SMEMC>>>(xin, w1q, sv1a, sv1c, conv1_b,
                                        nullptr, y1max, y1, 1024, 16);
    k_qy1<<<NB, 256>>>(y1, y1max, x2);
    k_conv<<<dim3(4, NB), 512, SMEMC>>>(x2, w2q, sv2, sv2c, conv2_b,
                                        y1max, nullptr, y2, 512, 32);

    k_final<<<NB, 256>>>(y2, wclsT, out);
}

// round 11
// speedup vs baseline: 3.1305x; 3.1305x over previous
#include <cuda_runtime.h>
#include <cuda_fp16.h>
#include <cstdint>

#define NB 256
#define HW 256
#define CH 256
#define OFF_C1 512
#define OFF_C2 (512 + 16777216)

// padded-row geometry: every 16-ic row is 48B (32B data + 16B pad) -> conflict-free ldmatrix
#define XROW    24                    // fp16 elements per row (48B)
#define XCHUNK  6144                  // 256 px * 24 el  (12288B)
#define WCHUNK  27648                 // 9*128*24 el     (55296B)
// conv smem map
#define XS0 0
#define XS1 12336                     // 12288 + 48 zero row
#define WS0 24672
#define WS1 79968
#define MBOFF 135264
#define SMEMC 135296

// ---------------- device scratch ----------------
__device__ __half g_XIN[(size_t)NB * 64 * XCHUNK];   // [img][64cc][256px][24]
__device__ __half g_Y1 [(size_t)NB * 64 * XCHUNK];
__device__ __half g_Y2 [(size_t)NB * 32 * XCHUNK];
__device__ float  g_invn1[NB * HW];
__device__ float  g_invn2[NB * HW];
__device__ __half g_W1[(size_t)8 * 64 * WCHUNK];     // [ocb][cc][9][128][24]
__device__ __half g_W2[(size_t)4 * 64 * WCHUNK];
__device__ float  g_wclsT[512 * 512];

// ---------------- PTX helpers ----------------
__device__ __forceinline__ uint32_t smem_u32(const void* p) {
    uint32_t a;
    asm("{ .reg .u64 t; cvta.to.shared.u64 t, %1; cvt.u32.u64 %0, t; }" : "=r"(a) : "l"(p));
    return a;
}
#define MBAR_INIT(a, c)  asm volatile("mbarrier.init.shared.b64 [%0], %1;" :: "r"(a), "r"((uint32_t)(c)) : "memory")
#define MBAR_EXPECT_TX(a, n) \
    asm volatile("mbarrier.arrive.expect_tx.shared.b64 _, [%0], %1;" :: "r"(a), "r"((uint32_t)(n)) : "memory")
#define MBAR_WAIT(a, par) do {                                                    \
    uint32_t _m = (a), _p = (par), _d;                                            \
    asm volatile("{\n\t.reg .pred p;\n\t"                                         \
        "mbarrier.try_wait.parity.acquire.cta.shared::cta.b64 p, [%1], %2;\n\t"   \
        "selp.b32 %0,1,0,p;\n\t}" : "=r"(_d) : "r"(_m), "r"(_p) : "memory");      \
    if (!_d) {                                                                    \
        asm volatile("{\n\t.reg .pred P1;\n\tWL_%=:\n\t"                          \
            "mbarrier.try_wait.parity.acquire.cta.shared::cta.b64 P1, [%0], %1, 0x989680;\n\t" \
            "@P1 bra.uni WD_%=;\n\tbra.uni WL_%=;\n\tWD_%=:\n\t}"                 \
            :: "r"(_m), "r"(_p) : "memory");                                      \
    }                                                                             \
} while (0)
#define BULK_G2S(dst, src, bytes, bar) \
    asm volatile("cp.async.bulk.shared::cta.global.mbarrier::complete_tx::bytes [%0], [%1], %2, [%3];" \
        :: "r"(dst), "l"(src), "r"((uint32_t)(bytes)), "r"(bar) : "memory")
#define LDSM4(r0, r1, r2, r3, a) \
    asm volatile("ldmatrix.sync.aligned.m8n8.x4.shared.b16 {%0,%1,%2,%3}, [%4];" \
        : "=r"(r0), "=r"(r1), "=r"(r2), "=r"(r3) : "r"(a))
// f16-accumulator HMMA: D,C packed half2 x2
__device__ __forceinline__ void mma16816h(uint32_t* c, const uint32_t* a, uint32_t b0, uint32_t b1) {
    asm volatile(
        "mma.sync.aligned.m16n8k16.row.col.f16.f16.f16.f16 "
        "{%0,%1}, {%2,%3,%4,%5}, {%6,%7}, {%0,%1};\n"
        : "+r"(c[0]), "+r"(c[1])
        : "r"(a[0]), "r"(a[1]), "r"(a[2]), "r"(a[3]), "r"(b0), "r"(b1));
}

// ---------------- K0: relu + channel norms + padded chunk layout ----------------
__global__ void k_norm(const float* __restrict__ f1, const float* __restrict__ f2,
                       __half* __restrict__ xin,
                       float* __restrict__ invn1, float* __restrict__ invn2) {
    int b = blockIdx.x, p = threadIdx.x;
    const float* f1b = f1 + (size_t)b * 65536;
    const float* f2b = f2 + (size_t)b * 65536;
    __half* xb = xin + (size_t)b * 64 * XCHUNK;
    float s1 = 0.f, s2 = 0.f;
    for (int ch = 0; ch < 16; ++ch) {
        __half h1[16], h2[16];
        #pragma unroll
        for (int i = 0; i < 16; ++i) {
            float v1 = fmaxf(f1b[(ch * 16 + i) * HW + p], 0.f);
            float v2 = fmaxf(f2b[(ch * 16 + i) * HW + p], 0.f);
            s1 += v1 * v1;  s2 += v2 * v2;
            h1[i] = __float2half_rn(v1);
            h2[i] = __float2half_rn(v2);
        }
        *(uint4*)&xb[(size_t)ch * XCHUNK + p * XROW]            = *(uint4*)&h1[0];
        *(uint4*)&xb[(size_t)ch * XCHUNK + p * XROW + 8]        = *(uint4*)&h1[8];
        *(uint4*)&xb[(size_t)(32 + ch) * XCHUNK + p * XROW]     = *(uint4*)&h2[0];
        *(uint4*)&xb[(size_t)(32 + ch) * XCHUNK + p * XROW + 8] = *(uint4*)&h2[8];
    }
    invn1[b * HW + p] = 1.0f / fmaxf(sqrtf(s1), 1e-12f);
    invn2[b * HW + p] = 1.0f / fmaxf(sqrtf(s2), 1e-12f);
}

// ---------------- weight prep: [ocb][cc][tap][128 oc][24] (48B padded rows) ----------------
__global__ void k_prepw(const float* __restrict__ w, __half* __restrict__ o,
                        int IC, int NCC, int total) {
    int idx = blockIdx.x * blockDim.x + threadIdx.x;
    if (idx >= total) return;
    int ii = idx & 15;
    int oo = (idx >> 4) & 127;
    int r  = idx >> 11;
    int tp = r % 9;  r /= 9;
    int cc = r % NCC; int ocb = r / NCC;
    int oc = ocb * 128 + oo;
    int ic = cc * 16 + ii;
    size_t dst = ((((size_t)(ocb * NCC + cc) * 9 + tp) * 128 + oo) * XROW) + ii;
    o[dst] = __float2half_rn(w[((size_t)oc * IC + ic) * 9 + tp]);
}

__global__ void k_prepcls(const float* __restrict__ w, float* __restrict__ o) {
    int idx = blockIdx.x * blockDim.x + threadIdx.x;
    if (idx >= 512 * 512) return;
    int ic = idx >> 9, oc = idx & 511;
    o[idx] = w[oc * 512 + ic];
}

// ---------------- K1: correlation GEMM (fp32 outputs + padded fp16 copies) ----------------
__global__ void __launch_bounds__(256) k_corr(
        const float* __restrict__ f1, const float* __restrict__ f2,
        float* __restrict__ out,
        const float* __restrict__ invn1, const float* __restrict__ invn2,
        __half* __restrict__ xin) {
    __shared__ float A_s[16][132];
    __shared__ float B_s[16][132];
    int b = blockIdx.x, q = blockIdx.y;
    int kb = (q >> 1) * 128, pb = (q & 1) * 128;
    int t = threadIdx.x, tx = t & 15, ty = t >> 4;
    const float* f1b = f1 + (size_t)b * 65536;
    const float* f2b = f2 + (size_t)b * 65536;
    float acc[8][8];
    #pragma unroll
    for (int i = 0; i < 8; ++i)
        #pragma unroll
        for (int j = 0; j < 8; ++j) acc[i][j] = 0.f;
    for (int cc = 0; cc < 16; ++cc) {
        #pragma unroll
        for (int u = 0; u < 8; ++u) {
            int e = t + 256 * u;
            int c = e >> 7, k = e & 127;
            A_s[c][k] = fmaxf(f2b[(cc * 16 + c) * HW + kb + k], 0.f);
            B_s[c][k] = fmaxf(f1b[(cc * 16 + c) * HW + pb + k], 0.f);
        }
        __syncthreads();
        #pragma unroll
        for (int c = 0; c < 16; ++c) {
            float4 a0 = *(const float4*)&A_s[c][ty * 8];
            float4 a1 = *(const float4*)&A_s[c][ty * 8 + 4];
            float4 b0 = *(const float4*)&B_s[c][tx * 8];
            float4 b1 = *(const float4*)&B_s[c][tx * 8 + 4];
            float av[8] = {a0.x, a0.y, a0.z, a0.w, a1.x, a1.y, a1.z, a1.w};
            float bv[8] = {b0.x, b0.y, b0.z, b0.w, b1.x, b1.y, b1.z, b1.w};
            #pragma unroll
            for (int i = 0; i < 8; ++i)
                #pragma unroll
                for (int j = 0; j < 8; ++j) acc[i][j] += av[i] * bv[j];
        }
        __syncthreads();
    }
    float ik[8], ip[8];
    #pragma unroll
    for (int i = 0; i < 8; ++i) ik[i] = invn2[b * HW + kb + ty * 8 + i];
    #pragma unroll
    for (int j = 0; j < 8; ++j) ip[j] = invn1[b * HW + pb + tx * 8 + j];

    float vm[8][8];
    #pragma unroll
    for (int i = 0; i < 8; ++i)
        #pragma unroll
        for (int j = 0; j < 8; ++j) vm[i][j] = acc[i][j] * ik[i] * ip[j];

    float* c1 = out + OFF_C1 + (size_t)b * 65536;
    float* c2 = out + OFF_C2 + (size_t)b * 65536;
    #pragma unroll
    for (int i = 0; i < 8; ++i) {
        int k = kb + ty * 8 + i;
        #pragma unroll
        for (int j = 0; j < 8; ++j) {
            int p = pb + tx * 8 + j;
            c1[k * HW + p] = vm[i][j];
            c2[p * HW + k] = vm[i][j];
        }
    }
    // fp16 copies into padded chunk layout: corr1 -> chunks 16..31, corr2 -> 48..63
    __half* xb = xin + (size_t)b * 64 * XCHUNK;
    int ch1 = 16 + (kb >> 4) + (ty >> 1);
    int sl1 = (ty & 1) * 8;
    #pragma unroll
    for (int j = 0; j < 8; ++j) {
        int p = pb + tx * 8 + j;
        __half h[8];
        #pragma unroll
        for (int i = 0; i < 8; ++i) h[i] = __float2half_rn(vm[i][j]);
        *(uint4*)&xb[(size_t)ch1 * XCHUNK + p * XROW + sl1] = *(uint4*)&h[0];
    }
    int ch2 = 48 + (pb >> 4) + (tx >> 1);
    int sl2 = (tx & 1) * 8;
    #pragma unroll
    for (int i = 0; i < 8; ++i) {
        int k = kb + ty * 8 + i;
        __half h[8];
        #pragma unroll
        for (int j = 0; j < 8; ++j) h[j] = __float2half_rn(vm[i][j]);
        *(uint4*)&xb[(size_t)ch2 * XCHUNK + k * XROW + sl2] = *(uint4*)&h[0];
    }
}

// ---------------- conv 3x3 implicit GEMM: f16-accum HMMA + bulk-copy double buffer ----------------
// grid (OC/128, NB), 512 threads = 16 warps (4M x 4N). Block tile M=128 oc, N=256 px.
__global__ void __launch_bounds__(512, 1) k_conv(
        const __half* __restrict__ Xin,  // [img][NCC][256][24]
        const __half* __restrict__ Wg,   // [ocb][NCC][9][128][24]
        const float* __restrict__ bias,
        __half* __restrict__ Y,          // [img][OC/16][256][24]
        int OC, int NCC) {
    extern __shared__ __align__(16) char sraw[];
    uint32_t sb = smem_u32(sraw);
    int img = blockIdx.y, ocb = blockIdx.x;
    int t = threadIdx.x, lane = t & 31, wid = t >> 5;
    int g = lane >> 2, tg = lane & 3;
    int wm = (wid & 3) * 32, wn = (wid >> 2) * 64;

    const char* xg = (const char*)(Xin + (size_t)img * NCC * XCHUNK);
    const char* wg = (const char*)(Wg + (size_t)ocb * NCC * WCHUNK);

    uint32_t FB0 = sb + MBOFF, FB1 = sb + MBOFF + 8;
    if (t == 0) { MBAR_INIT(FB0, 1); MBAR_INIT(FB1, 1); }
    // zero halo rows (offset 12288 of both X buffers)
    if (t < 24) {
        int bi = t / 12, w = t % 12;
        *(uint32_t*)(sraw + (bi ? XS1 : XS0) + 12288 + w * 4) = 0u;
    }
    __syncthreads();
    if (t == 0) {
        #pragma unroll
        for (int s = 0; s < 2; ++s) {
            uint32_t fb = s ? FB1 : FB0;
            MBAR_EXPECT_TX(fb, 12288 + 55296);
            BULK_G2S(sb + (s ? XS1 : XS0), xg + (size_t)s * 12288, 12288, fb);
            BULK_G2S(sb + (s ? WS1 : WS0), wg + (size_t)s * 55296, 55296, fb);
        }
    }

    // per-lane ldmatrix address prep
    int r8 = lane & 7;
    uint32_t q1 = (lane >> 3) & 1;        // k-half (col +16B)
    int      q2 = (lane >> 4) & 1;        // j vs j+1
    uint32_t arel = (uint32_t)(wm + r8 + ((lane & 8) ? 8 : 0)) * 48 + ((lane & 16) ? 16 : 0);
    uint32_t xrel[4], mv[4];
    #pragma unroll
    for (int jj = 0; jj < 4; ++jj) {
        int px = wn + (2 * jj + q2) * 8 + r8;
        xrel[jj] = (uint32_t)px * 48 + q1 * 16;
        int xx = px & 15, yy = px >> 4;
        uint32_t m = 0;
        #pragma unroll
        for (int tp = 0; tp < 9; ++tp) {
            int dy = tp / 3 - 1, dx = tp % 3 - 1;
            if ((unsigned)(xx + dx) < 16u && (unsigned)(yy + dy) < 16u) m |= 1u << tp;
        }
        mv[jj] = m;
    }

    uint32_t acc[2][8][2];     // packed half2 accumulators
    #pragma unroll
    for (int mi = 0; mi < 2; ++mi)
        #pragma unroll
        for (int j = 0; j < 8; ++j) { acc[mi][j][0] = 0u; acc[mi][j][1] = 0u; }

    for (int cc = 0; cc < NCC; ++cc) {
        int p = cc & 1, ph = (cc >> 1) & 1;
        MBAR_WAIT(p ? FB1 : FB0, ph);

        uint32_t Xa = sb + (p ? XS1 : XS0);
        uint32_t Wa = sb + (p ? WS1 : WS0);
        uint32_t za = Xa + 12288 + q1 * 16;
        uint32_t bb0 = Xa + xrel[0], bb1 = Xa + xrel[1];
        uint32_t bb2 = Xa + xrel[2], bb3 = Xa + xrel[3];
        uint32_t aA = Wa + arel;

        #pragma unroll
        for (int tp = 0; tp < 9; ++tp) {
            const int dy = tp / 3 - 1, dx = tp % 3 - 1;
            const int off = (dy * 16 + dx) * 48;
            uint32_t a0[4], a1[4];
            LDSM4(a0[0], a0[1], a0[2], a0[3], aA + tp * 6144);
            LDSM4(a1[0], a1[1], a1[2], a1[3], aA + tp * 6144 + 768);
            uint32_t bbv[4] = {bb0, bb1, bb2, bb3};
            #pragma unroll
            for (int jj = 0; jj < 4; ++jj) {
                uint32_t ba = ((mv[jj] >> tp) & 1u) ? (uint32_t)(bbv[jj] + off) : za;
                uint32_t b0, b1, b2, b3;
                LDSM4(b0, b1, b2, b3, ba);
                mma16816h(acc[0][2 * jj],     a0, b0, b1);
                mma16816h(acc[1][2 * jj],     a1, b0, b1);
                mma16816h(acc[0][2 * jj + 1], a0, b2, b3);
                mma16816h(acc[1][2 * jj + 1], a1, b2, b3);
            }
        }

        __syncthreads();                     // all warps done with buffer p
        if (t == 0 && cc + 2 < NCC) {
            int nn = cc + 2;
            uint32_t fb = p ? FB1 : FB0;
            MBAR_EXPECT_TX(fb, 12288 + 55296);
            BULK_G2S(Xa, xg + (size_t)nn * 12288, 12288, fb);
            BULK_G2S(Wa, wg + (size_t)nn * 55296, 55296, fb);
        }
    }

    // epilogue: bias + relu, transpose through smem, coalesced 16B stores
    __syncthreads();
    __half* Sh = (__half*)sraw;   // [256 px][136]
    #pragma unroll
    for (int mi = 0; mi < 2; ++mi) {
        int ocl = wm + mi * 16 + g;
        float bz0 = bias[ocb * 128 + ocl];
        float bz1 = bias[ocb * 128 + ocl + 8];
        #pragma unroll
        for (int j = 0; j < 8; ++j) {
            int px = wn + j * 8 + 2 * tg;
            __half2 h01 = *(__half2*)&acc[mi][j][0];   // row ocl, px, px+1
            __half2 h23 = *(__half2*)&acc[mi][j][1];   // row ocl+8
            Sh[px * 136 + ocl]           = __float2half_rn(fmaxf(__low2float(h01)  + bz0, 0.f));
            Sh[(px + 1) * 136 + ocl]     = __float2half_rn(fmaxf(__high2float(h01) + bz0, 0.f));
            Sh[px * 136 + ocl + 8]       = __float2half_rn(fmaxf(__low2float(h23)  + bz1, 0.f));
            Sh[(px + 1) * 136 + ocl + 8] = __float2half_rn(fmaxf(__high2float(h23) + bz1, 0.f));
        }
    }
    __syncthreads();
    __half* Yb = Y + ((size_t)img * (OC >> 4) + ocb * 8) * XCHUNK;
    #pragma unroll
    for (int k2 = 0; k2 < 8; ++k2) {
        int idx = t + 512 * k2;               // 4096 = 8 chunks * 256 px * 2 halves
        int c8 = idx >> 9, rem = idx & 511, px = rem >> 1, hf = rem & 1;
        uint4 v = *(uint4*)&Sh[px * 136 + c8 * 16 + hf * 8];
        *(uint4*)&Yb[((size_t)c8 * 256 + px) * XROW + hf * 8] = v;
    }
}

// ---------------- final head: 1x1 (diag) + avgpool + softmax ----------------
__global__ void k_final(const __half* __restrict__ Y2,
                        const float* __restrict__ wT,
                        float* __restrict__ out) {
    int b = blockIdx.x, p = threadIdx.x;
    const __half* yb = Y2 + (size_t)b * 32 * XCHUNK;
    float a0 = 0.f, a1 = 0.f;
    for (int c = 0; c < 32; ++c) {
        __half h[16];
        *(uint4*)&h[0] = *(const uint4*)&yb[((size_t)c * 256 + p) * XROW];
        *(uint4*)&h[8] = *(const uint4*)&yb[((size_t)c * 256 + p) * XROW + 8];
        const float* wr = wT + (size_t)c * 16 * 512 + p;
        #pragma unroll
        for (int i = 0; i < 16; ++i) {
            float y = __half2float(h[i]);
            a0 += wr[i * 512] * y;
            a1 += wr[i * 512 + 256] * y;
        }
    }
    a0 = fmaxf(a0, 0.f);
    a1 = fmaxf(a1, 0.f);
    __shared__ float s0[256], s1[256];
    s0[p] = a0; s1[p] = a1;
    __syncthreads();
    for (int st = 128; st > 0; st >>= 1) {
        if (p < st) { s0[p] += s0[p + st]; s1[p] += s1[p + st]; }
        __syncthreads();
    }
    if (p == 0) {
        float m0 = s0[0] * (1.0f / 256.0f);
        float m1 = s1[0] * (1.0f / 256.0f);
        float mx = fmaxf(m0, m1);
        float e0 = expf(m0 - mx), e1 = expf(m1 - mx);
        float inv = 1.0f / (e0 + e1);
        out[b * 2 + 0] = e0 * inv;
        out[b * 2 + 1] = e1 * inv;
    }
}

// ---------------- launch ----------------
extern "C" void kernel_launch(void* const* d_in, const int* in_sizes, int n_in,
                              void* d_out, int out_size) {
    const float* f1      = (const float*)d_in[0];
    const float* f2      = (const float*)d_in[1];
    const float* conv1_w = (const float*)d_in[2];
    const float* conv1_b = (const float*)d_in[3];
    const float* conv2_w = (const float*)d_in[4];
    const float* conv2_b = (const float*)d_in[5];
    const float* cls_w   = (const float*)d_in[6];
    float* out = (float*)d_out;

    __half *xin, *y1, *y2, *w1, *w2;
    float *invn1, *invn2, *wclsT;
    cudaGetSymbolAddress((void**)&xin,   g_XIN);
    cudaGetSymbolAddress((void**)&y1,    g_Y1);
    cudaGetSymbolAddress((void**)&y2,    g_Y2);
    cudaGetSymbolAddress((void**)&w1,    g_W1);
    cudaGetSymbolAddress((void**)&w2,    g_W2);
    cudaGetSymbolAddress((void**)&invn1, g_invn1);
    cudaGetSymbolAddress((void**)&invn2, g_invn2);
    cudaGetSymbolAddress((void**)&wclsT, g_wclsT);

    cudaFuncSetAttribute(k_conv, cudaFuncAttributeMaxDynamicSharedMemorySize, SMEMC);

    k_norm<<<NB, 256>>>(f1, f2, xin, invn1, invn2);
    {
        int tot1 = 8 * 64 * 9 * 2048;   // logical elements (pre-pad)
        k_prepw<<<(tot1 + 255) / 256, 256>>>(conv1_w, w1, 1024, 64, tot1);
        int tot2 = 4 * 64 * 9 * 2048;
        k_prepw<<<(tot2 + 255) / 256, 256>>>(conv2_w, w2, 1024, 64, tot2);
        k_prepcls<<<(512 * 512 + 255) / 256, 256>>>(cls_w, wclsT);
    }
    k_corr<<<dim3(NB, 4), 256>>>(f1, f2, out, invn1, invn2, xin);

    k_conv<<<dim3(8, NB), 512, SMEMC>>>(xin, w1, conv1_b, y1, 1024, 64);
    k_conv<<<dim3(4, NB), 512, SMEMC>>>(y1,  w2, conv2_b, y2,  512, 64);

    k_final<<<NB, 256>>>(y2, wclsT, out);
}